// round 3
// baseline (speedup 1.0000x reference)
#include <cuda_runtime.h>
#include <math.h>

// Problem-fixed shapes
#define NNODES 100000
#define NEDGES 1600000
#define NGRAPH 512

// ---------------- scratch (device globals; no allocation) ----------------
__device__ int   d_deg[NNODES];
__device__ int   d_rowptr[NNODES + 1];
__device__ int   d_cursor[NNODES];
__device__ int   d_col[NEDGES];
__device__ float d_dinv[NNODES];
__device__ float d_bufA[(size_t)NNODES * 128];
__device__ float d_bufB[(size_t)NNODES * 128];
__device__ float d_g[NGRAPH * 128];
__device__ int   d_bsum[256];

// ---------------- CSR build ----------------
__global__ void k_zero_deg() {
    int i = blockIdx.x * blockDim.x + threadIdx.x;
    if (i < NNODES) d_deg[i] = 0;
}

__global__ void k_deg(const int* __restrict__ dst) {
    int e = blockIdx.x * blockDim.x + threadIdx.x;
    if (e < NEDGES) atomicAdd(&d_deg[dst[e]], 1);
}

// block-local exclusive scan (512 elems per block)
__global__ void k_scan1() {
    __shared__ int s[512];
    int i = blockIdx.x * 512 + threadIdx.x;
    int v = (i < NNODES) ? d_deg[i] : 0;
    s[threadIdx.x] = v;
    __syncthreads();
    for (int off = 1; off < 512; off <<= 1) {
        int t = (threadIdx.x >= off) ? s[threadIdx.x - off] : 0;
        __syncthreads();
        s[threadIdx.x] += t;
        __syncthreads();
    }
    if (i < NNODES) d_rowptr[i] = s[threadIdx.x] - v;  // exclusive
    if (threadIdx.x == 511) d_bsum[blockIdx.x] = s[511];
}

__global__ void k_scan2(int nblk) {
    if (threadIdx.x == 0 && blockIdx.x == 0) {
        int acc = 0;
        for (int b = 0; b < nblk; b++) {
            int t = d_bsum[b];
            d_bsum[b] = acc;
            acc += t;
        }
        d_rowptr[NNODES] = acc;
    }
}

__global__ void k_scan3() {
    int i = blockIdx.x * 512 + threadIdx.x;
    if (i < NNODES) {
        int r = d_rowptr[i] + d_bsum[blockIdx.x];
        d_rowptr[i] = r;
        d_cursor[i] = r;
    }
}

__global__ void k_dinv() {
    int i = blockIdx.x * blockDim.x + threadIdx.x;
    if (i < NNODES) d_dinv[i] = rsqrtf((float)(d_deg[i] + 1));  // +1 = self loop
}

__global__ void k_scatter(const int* __restrict__ src,
                          const int* __restrict__ dst) {
    int e = blockIdx.x * blockDim.x + threadIdx.x;
    if (e < NEDGES) {
        int d = dst[e];
        int pos = atomicAdd(&d_cursor[d], 1);
        d_col[pos] = src[e];
    }
}

// ---------------- dense GEMM with dinv row-scale epilogue ----------------
// Y[row] = dinv[row] * (H[row] @ W).  H = Hext if non-null else d_bufB.
// Output always d_bufA.  H:[n,FIN], W:[FIN,FOUT] row-major.
template <int FIN, int FOUT>
__global__ void k_gemm_scale(const float* __restrict__ Hext,
                             const float* __restrict__ W) {
    const float* __restrict__ H = Hext ? Hext : (const float*)d_bufB;
    float* __restrict__ Y = d_bufA;

    __shared__ float Ws[FIN * FOUT];
    __shared__ float As[64][33];
    for (int i = threadIdx.x; i < FIN * FOUT; i += 256) Ws[i] = W[i];

    const int row0 = blockIdx.x * 64;
    const int tr = threadIdx.x % 64;  // row within tile
    const int tc = threadIdx.x / 64;  // 0..3
    constexpr int CPT = FOUT / 4;     // cols per thread
    float acc[CPT];
#pragma unroll
    for (int j = 0; j < CPT; j++) acc[j] = 0.f;
    const int row = row0 + tr;

    for (int k0 = 0; k0 < FIN; k0 += 32) {
        __syncthreads();
        for (int i = threadIdx.x; i < 64 * 32; i += 256) {
            int r = i / 32, c = i % 32;
            int gr = row0 + r;
            As[r][c] = (gr < NNODES) ? H[(size_t)gr * FIN + k0 + c] : 0.f;
        }
        __syncthreads();
#pragma unroll
        for (int k = 0; k < 32; k++) {
            float a = As[tr][k];
#pragma unroll
            for (int j = 0; j < CPT; j++)
                acc[j] += a * Ws[(k0 + k) * FOUT + tc * CPT + j];
        }
    }
    if (row < NNODES) {
        float sc = d_dinv[row];
#pragma unroll
        for (int j = 0; j < CPT; j++)
            Y[(size_t)row * FOUT + tc * CPT + j] = acc[j] * sc;
    }
}

// ---------------- sparse aggregation (gather, warp per node) ----------------
// O[i] = relu?( dinv[i] * (Y[i] + sum_{j->i} Y[j]) + b )
// Reads d_bufA, writes d_bufB.
template <int F, bool RELU>
__global__ void k_agg(const float* __restrict__ bias) {
    const float* __restrict__ Y = d_bufA;
    float* __restrict__ O = d_bufB;

    int warp = (blockIdx.x * blockDim.x + threadIdx.x) >> 5;
    if (warp >= NNODES) return;
    int lane = threadIdx.x & 31;
    constexpr int V = F / 32;
    float acc[V];

    const float* pself = Y + (size_t)warp * F + lane * V;
    if constexpr (V == 4) {
        float4 t = *reinterpret_cast<const float4*>(pself);
        acc[0] = t.x; acc[1] = t.y; acc[2] = t.z; acc[3] = t.w;
    } else if constexpr (V == 2) {
        float2 t = *reinterpret_cast<const float2*>(pself);
        acc[0] = t.x; acc[1] = t.y;
    } else {
        acc[0] = *pself;
    }

    int s = d_rowptr[warp];
    int e = d_rowptr[warp + 1];
#pragma unroll 2
    for (int j = s; j < e; j++) {
        int c = __ldg(&d_col[j]);
        const float* p = Y + (size_t)c * F + lane * V;
        if constexpr (V == 4) {
            float4 t = *reinterpret_cast<const float4*>(p);
            acc[0] += t.x; acc[1] += t.y; acc[2] += t.z; acc[3] += t.w;
        } else if constexpr (V == 2) {
            float2 t = *reinterpret_cast<const float2*>(p);
            acc[0] += t.x; acc[1] += t.y;
        } else {
            acc[0] += *p;
        }
    }

    float sc = d_dinv[warp];
#pragma unroll
    for (int v = 0; v < V; v++) {
        float o = sc * acc[v] + bias[lane * V + v];
        if (RELU) o = fmaxf(o, 0.f);
        O[(size_t)warp * F + lane * V + v] = o;
    }
}

// ---------------- pooling (exploits sorted batch) ----------------
__global__ void k_zero_g() {
    int i = blockIdx.x * blockDim.x + threadIdx.x;
    if (i < NGRAPH * 128) d_g[i] = 0.f;
}

__global__ void k_pool(const int* __restrict__ batch) {
    const float* __restrict__ H = d_bufB;
    int i0 = blockIdx.x * 128;
    if (i0 >= NNODES) return;
    int i1 = min(i0 + 128, NNODES);
    int f = threadIdx.x;  // 0..127
    int cur = batch[i0];
    float acc = 0.f;
    for (int i = i0; i < i1; i++) {
        int b = batch[i];
        if (b != cur) {
            atomicAdd(&d_g[cur * 128 + f], acc);
            acc = 0.f;
            cur = b;
        }
        acc += H[(size_t)i * 128 + f];
    }
    atomicAdd(&d_g[cur * 128 + f], acc);
}

// ---------------- final MLP + log_softmax ----------------
__global__ void k_mlp(const float* __restrict__ Wl1, const float* __restrict__ bl1,
                      const float* __restrict__ Wl2, const float* __restrict__ bl2,
                      float* __restrict__ out) {
    __shared__ float row[128];
    __shared__ float hid[64];
    __shared__ float o[10];
    int b = blockIdx.x, t = threadIdx.x;
    row[t] = d_g[b * 128 + t];
    __syncthreads();
    if (t < 64) {
        float a = bl1[t];
        for (int k = 0; k < 128; k++) a += row[k] * Wl1[k * 64 + t];
        hid[t] = fmaxf(a, 0.f);
    }
    __syncthreads();
    if (t < 10) {
        float a = bl2[t];
        for (int k = 0; k < 64; k++) a += hid[k] * Wl2[k * 10 + t];
        o[t] = a;
    }
    __syncthreads();
    if (t == 0) {
        float m = -INFINITY;
        for (int i = 0; i < 10; i++) m = fmaxf(m, o[i]);
        float s = 0.f;
        for (int i = 0; i < 10; i++) s += expf(o[i] - m);
        float l = m + logf(s);
        for (int i = 0; i < 10; i++) out[b * 10 + i] = o[i] - l;
    }
}

// ---------------- launch ----------------
extern "C" void kernel_launch(void* const* d_in, const int* in_sizes, int n_in,
                              void* d_out, int out_size) {
    const float* x     = (const float*)d_in[0];
    const int*   ei    = (const int*)d_in[1];   // [2, E] int32 (JAX x64 disabled)
    const int*   batch = (const int*)d_in[2];   // int32
    const float* W1  = (const float*)d_in[3];
    const float* b1  = (const float*)d_in[4];
    const float* W2  = (const float*)d_in[5];
    const float* b2  = (const float*)d_in[6];
    const float* W3  = (const float*)d_in[7];
    const float* b3  = (const float*)d_in[8];
    const float* Wl1 = (const float*)d_in[9];
    const float* bl1 = (const float*)d_in[10];
    const float* Wl2 = (const float*)d_in[11];
    const float* bl2 = (const float*)d_in[12];
    float* out = (float*)d_out;

    const int* src = ei;
    const int* dst = ei + NEDGES;

    const int NBLK_SCAN = (NNODES + 511) / 512;  // 196
    const int EBLK = (NEDGES + 255) / 256;       // 6250
    const int NB64 = (NNODES + 63) / 64;         // 1563
    const int AGGBLK = (NNODES * 32 + 255) / 256;

    // CSR build + dinv
    k_zero_deg<<<(NNODES + 255) / 256, 256>>>();
    k_deg<<<EBLK, 256>>>(dst);
    k_scan1<<<NBLK_SCAN, 512>>>();
    k_scan2<<<1, 32>>>(NBLK_SCAN);
    k_scan3<<<NBLK_SCAN, 512>>>();
    k_dinv<<<(NNODES + 255) / 256, 256>>>();
    k_scatter<<<EBLK, 256>>>(src, dst);

    // Layer 1: 128 -> 32   (x -> bufA -> bufB)
    k_gemm_scale<128, 32><<<NB64, 256>>>(x, W1);
    k_agg<32, true><<<AGGBLK, 256>>>(b1);
    // Layer 2: 32 -> 64    (bufB -> bufA -> bufB)
    k_gemm_scale<32, 64><<<NB64, 256>>>(nullptr, W2);
    k_agg<64, true><<<AGGBLK, 256>>>(b2);
    // Layer 3: 64 -> 128   (bufB -> bufA -> bufB)
    k_gemm_scale<64, 128><<<NB64, 256>>>(nullptr, W3);
    k_agg<128, false><<<AGGBLK, 256>>>(b3);

    // Pool + MLP head
    k_zero_g<<<(NGRAPH * 128 + 255) / 256, 256>>>();
    k_pool<<<(NNODES + 127) / 128, 128>>>(batch);
    k_mlp<<<NGRAPH, 128>>>(Wl1, bl1, Wl2, bl2, out);
}

// round 4
// speedup vs baseline: 1.5683x; 1.5683x over previous
#include <cuda_runtime.h>
#include <math.h>

// Problem-fixed shapes
#define NNODES 100000
#define NEDGES 1600000
#define NGRAPH 512

// ---------------- scratch (device globals; no allocation) ----------------
__device__ int   d_deg[NNODES];
__device__ int   d_rowptr[NNODES + 1];
__device__ int   d_cursor[NNODES];
__device__ int   d_col[NEDGES];
__device__ float d_dinv[NNODES];
__device__ float d_bufA[(size_t)NNODES * 128];
__device__ float d_bufB[(size_t)NNODES * 128];
__device__ float d_g[NGRAPH * 128];
__device__ int   d_bsum[256];

// ---------------- CSR build ----------------
__global__ void k_zero() {
    int i = blockIdx.x * blockDim.x + threadIdx.x;
    if (i < NNODES) d_deg[i] = 0;
    if (i < NGRAPH * 128) d_g[i] = 0.f;
}

__global__ void k_deg(const int* __restrict__ dst) {
    int e = blockIdx.x * blockDim.x + threadIdx.x;
    if (e < NEDGES) atomicAdd(&d_deg[dst[e]], 1);
}

// block-local exclusive scan (512 elems per block)
__global__ void k_scan1() {
    __shared__ int s[512];
    int i = blockIdx.x * 512 + threadIdx.x;
    int v = (i < NNODES) ? d_deg[i] : 0;
    s[threadIdx.x] = v;
    __syncthreads();
    for (int off = 1; off < 512; off <<= 1) {
        int t = (threadIdx.x >= off) ? s[threadIdx.x - off] : 0;
        __syncthreads();
        s[threadIdx.x] += t;
        __syncthreads();
    }
    if (i < NNODES) d_rowptr[i] = s[threadIdx.x] - v;  // exclusive within block
    if (threadIdx.x == 511) d_bsum[blockIdx.x] = s[511];
}

// parallel exclusive scan over block sums (nblk <= 256)
__global__ void k_scan2(int nblk) {
    __shared__ int s[256];
    int t = threadIdx.x;
    int v = (t < nblk) ? d_bsum[t] : 0;
    s[t] = v;
    __syncthreads();
    for (int off = 1; off < 256; off <<= 1) {
        int u = (t >= off) ? s[t - off] : 0;
        __syncthreads();
        s[t] += u;
        __syncthreads();
    }
    if (t < nblk) d_bsum[t] = s[t] - v;  // exclusive
    if (t == nblk - 1) d_rowptr[NNODES] = s[t];
}

__global__ void k_scan3() {
    int i = blockIdx.x * 512 + threadIdx.x;
    if (i < NNODES) {
        int r = d_rowptr[i] + d_bsum[blockIdx.x];
        d_rowptr[i] = r;
        d_cursor[i] = r;
        d_dinv[i] = rsqrtf((float)(d_deg[i] + 1));  // +1 = self loop
    }
}

__global__ void k_scatter(const int* __restrict__ src,
                          const int* __restrict__ dst) {
    int e = blockIdx.x * blockDim.x + threadIdx.x;
    if (e < NEDGES) {
        int d = dst[e];
        int pos = atomicAdd(&d_cursor[d], 1);
        d_col[pos] = src[e];
    }
}

// ---------------- register-tiled GEMM ----------------
// Y = epilogue(H @ W).  H:[n,FIN] row-major (SRC_EXT ? Hext : d_bufA),
// Y:[n,FOUT] (DST_A ? d_bufA : d_bufB).
// Thread tile 4 x TN. Block tile BM x FOUT. 256 threads.
// Epilogue: v = acc; if BIAS v += b; if RELU v = max(v,0); if OUTD v *= dinv[row].
template <int FIN, int FOUT, int BM, int TN,
          bool BIAS, bool RELU, bool OUTD, bool SRC_EXT, bool DST_A>
__launch_bounds__(256)
__global__ void k_gemm(const float* __restrict__ Hext,
                       const float* __restrict__ W,
                       const float* __restrict__ bias) {
    const float* __restrict__ H = SRC_EXT ? Hext : (const float*)d_bufA;
    float* __restrict__ Y = DST_A ? d_bufA : d_bufB;

    constexpr int KT = 32;
    __shared__ float Ws[FIN][FOUT];
    __shared__ float As[KT][BM + 4];  // k-major, +4 keeps 16B align & shifts banks

    for (int i = threadIdx.x; i < FIN * FOUT; i += 256)
        ((float*)Ws)[i] = W[i];

    constexpr int CG = FOUT / TN;  // col groups
    constexpr int RG = BM / 4;     // row groups
    static_assert(CG * RG == 256, "tiling");
    const int tc = threadIdx.x % CG;
    const int tr = threadIdx.x / CG;
    const int row0 = blockIdx.x * BM;

    float acc[4][TN];
#pragma unroll
    for (int m = 0; m < 4; m++)
#pragma unroll
        for (int n = 0; n < TN; n++) acc[m][n] = 0.f;

    for (int k0 = 0; k0 < FIN; k0 += KT) {
        __syncthreads();
        // load H tile [BM][KT] transposed into As[k][m]
        constexpr int LOADS = BM * KT / 4;  // float4 per thread-chunk
        for (int i = threadIdx.x; i < LOADS; i += 256) {
            int r = i / (KT / 4);
            int kc = (i % (KT / 4)) * 4;
            int gr = row0 + r;
            float4 v = (gr < NNODES)
                ? *reinterpret_cast<const float4*>(&H[(size_t)gr * FIN + k0 + kc])
                : make_float4(0.f, 0.f, 0.f, 0.f);
            As[kc + 0][r] = v.x;
            As[kc + 1][r] = v.y;
            As[kc + 2][r] = v.z;
            As[kc + 3][r] = v.w;
        }
        __syncthreads();
#pragma unroll
        for (int k = 0; k < KT; k++) {
            float a[4];
            const float4 av = *reinterpret_cast<const float4*>(&As[k][tr * 4]);
            a[0] = av.x; a[1] = av.y; a[2] = av.z; a[3] = av.w;
            float w[TN];
#pragma unroll
            for (int n = 0; n < TN; n += 4) {
                const float4 wv = *reinterpret_cast<const float4*>(&Ws[k0 + k][tc * TN + n]);
                w[n + 0] = wv.x; w[n + 1] = wv.y; w[n + 2] = wv.z; w[n + 3] = wv.w;
            }
#pragma unroll
            for (int m = 0; m < 4; m++)
#pragma unroll
                for (int n = 0; n < TN; n++)
                    acc[m][n] += a[m] * w[n];
        }
    }

    float b[TN];
    if (BIAS) {
#pragma unroll
        for (int n = 0; n < TN; n++) b[n] = bias[tc * TN + n];
    }
#pragma unroll
    for (int m = 0; m < 4; m++) {
        int row = row0 + tr * 4 + m;
        if (row < NNODES) {
            float d = OUTD ? d_dinv[row] : 1.f;
#pragma unroll
            for (int n = 0; n < TN; n += 4) {
                float4 v;
                float t0 = acc[m][n + 0], t1 = acc[m][n + 1],
                      t2 = acc[m][n + 2], t3 = acc[m][n + 3];
                if (BIAS) { t0 += b[n]; t1 += b[n + 1]; t2 += b[n + 2]; t3 += b[n + 3]; }
                if (RELU) { t0 = fmaxf(t0, 0.f); t1 = fmaxf(t1, 0.f);
                            t2 = fmaxf(t2, 0.f); t3 = fmaxf(t3, 0.f); }
                if (OUTD) { t0 *= d; t1 *= d; t2 *= d; t3 *= d; }
                v.x = t0; v.y = t1; v.z = t2; v.w = t3;
                *reinterpret_cast<float4*>(&Y[(size_t)row * FOUT + tc * TN + n]) = v;
            }
        }
    }
}

// ---------------- sparse aggregation (gather, warp per node) ----------------
// acc = sum over {self} U nbrs of SRC rows; then
// v = d*acc; if BIAS v += b; if RELU v = max(v,0); if POSTD v *= d.
// SRC = (A_SRC ? bufA : bufB), DST = other.
template <int F, bool A_SRC, bool BIAS, bool RELU, bool POSTD>
__launch_bounds__(256)
__global__ void k_agg(const float* __restrict__ bias) {
    const float* __restrict__ Y = A_SRC ? (const float*)d_bufA : (const float*)d_bufB;
    float* __restrict__ O = A_SRC ? d_bufB : d_bufA;

    int warp = (blockIdx.x * 256 + threadIdx.x) >> 5;
    if (warp >= NNODES) return;
    int lane = threadIdx.x & 31;
    constexpr int V = F / 32;
    float acc[V];

    const float* pself = Y + (size_t)warp * F + lane * V;
    if constexpr (V == 2) {
        float2 t = *reinterpret_cast<const float2*>(pself);
        acc[0] = t.x; acc[1] = t.y;
    } else {
        acc[0] = *pself;
    }

    int s = __ldg(&d_rowptr[warp]);
    int e = __ldg(&d_rowptr[warp + 1]);
#pragma unroll 4
    for (int j = s; j < e; j++) {
        int c = __ldg(&d_col[j]);
        const float* p = Y + (size_t)c * F + lane * V;
        if constexpr (V == 2) {
            float2 t = *reinterpret_cast<const float2*>(p);
            acc[0] += t.x; acc[1] += t.y;
        } else {
            acc[0] += *p;
        }
    }

    float d = d_dinv[warp];
    float o[V];
#pragma unroll
    for (int v = 0; v < V; v++) {
        float t = d * acc[v];
        if (BIAS) t += bias[lane * V + v];
        if (RELU) t = fmaxf(t, 0.f);
        if (POSTD) t *= d;
        o[v] = t;
    }
    if constexpr (V == 2) {
        *reinterpret_cast<float2*>(&O[(size_t)warp * F + lane * 2]) = make_float2(o[0], o[1]);
    } else {
        O[(size_t)warp * F + lane] = o[0];
    }
}

// ---------------- pooling (exploits sorted batch) ----------------
__global__ void k_pool(const int* __restrict__ batch) {
    const float* __restrict__ H = d_bufB;
    int i0 = blockIdx.x * 128;
    if (i0 >= NNODES) return;
    int i1 = min(i0 + 128, NNODES);
    int f = threadIdx.x;  // 0..127
    int cur = batch[i0];
    float acc = 0.f;
    for (int i = i0; i < i1; i++) {
        int b = batch[i];
        if (b != cur) {
            atomicAdd(&d_g[cur * 128 + f], acc);
            acc = 0.f;
            cur = b;
        }
        acc += H[(size_t)i * 128 + f];
    }
    atomicAdd(&d_g[cur * 128 + f], acc);
}

// ---------------- final MLP + log_softmax ----------------
__global__ void k_mlp(const float* __restrict__ Wl1, const float* __restrict__ bl1,
                      const float* __restrict__ Wl2, const float* __restrict__ bl2,
                      float* __restrict__ out) {
    __shared__ float row[128];
    __shared__ float hid[64];
    __shared__ float o[10];
    int b = blockIdx.x, t = threadIdx.x;
    row[t] = d_g[b * 128 + t];
    __syncthreads();
    if (t < 64) {
        float a = bl1[t];
        for (int k = 0; k < 128; k++) a += row[k] * Wl1[k * 64 + t];
        hid[t] = fmaxf(a, 0.f);
    }
    __syncthreads();
    if (t < 10) {
        float a = bl2[t];
        for (int k = 0; k < 64; k++) a += hid[k] * Wl2[k * 10 + t];
        o[t] = a;
    }
    __syncthreads();
    if (t == 0) {
        float m = -INFINITY;
        for (int i = 0; i < 10; i++) m = fmaxf(m, o[i]);
        float s = 0.f;
        for (int i = 0; i < 10; i++) s += expf(o[i] - m);
        float l = m + logf(s);
        for (int i = 0; i < 10; i++) out[b * 10 + i] = o[i] - l;
    }
}

// ---------------- launch ----------------
extern "C" void kernel_launch(void* const* d_in, const int* in_sizes, int n_in,
                              void* d_out, int out_size) {
    const float* x     = (const float*)d_in[0];
    const int*   ei    = (const int*)d_in[1];   // [2, E] int32
    const int*   batch = (const int*)d_in[2];   // int32
    const float* W1  = (const float*)d_in[3];
    const float* b1  = (const float*)d_in[4];
    const float* W2  = (const float*)d_in[5];
    const float* b2  = (const float*)d_in[6];
    const float* W3  = (const float*)d_in[7];
    const float* b3  = (const float*)d_in[8];
    const float* Wl1 = (const float*)d_in[9];
    const float* bl1 = (const float*)d_in[10];
    const float* Wl2 = (const float*)d_in[11];
    const float* bl2 = (const float*)d_in[12];
    float* out = (float*)d_out;

    const int* src = ei;
    const int* dst = ei + NEDGES;

    const int NBLK_SCAN = (NNODES + 511) / 512;  // 196
    const int EBLK = (NEDGES + 255) / 256;       // 6250
    const int AGGBLK = (NNODES * 32 + 255) / 256;

    // CSR build + dinv (+ zero pooled output)
    k_zero<<<(NNODES + 255) / 256, 256>>>();
    k_deg<<<EBLK, 256>>>(dst);
    k_scan1<<<NBLK_SCAN, 512>>>();
    k_scan2<<<1, 256>>>(NBLK_SCAN);
    k_scan3<<<NBLK_SCAN, 512>>>();
    k_scatter<<<EBLK, 256>>>(src, dst);

    // L1: Y = d*(x@W1)                    x -> A      (FIN=128,FOUT=32,BM=128,TN=4)
    k_gemm<128, 32, 128, 4, false, false, true, true, true>
        <<<(NNODES + 127) / 128, 256>>>(x, W1, nullptr);
    // agg1: P1 = d*relu(d*sum + b1)       A -> B
    k_agg<32, true, true, true, true><<<AGGBLK, 256>>>(b1);
    // agg2: Q2 = d*sum(P1)                B -> A
    k_agg<32, false, false, false, false><<<AGGBLK, 256>>>(nullptr);
    // L2: P2 = d*relu(Q2@W2 + b2)         A -> B      (FIN=32,FOUT=64,BM=64,TN=4)
    k_gemm<32, 64, 64, 4, true, true, true, false, false>
        <<<(NNODES + 63) / 64, 256>>>(nullptr, W2, b2);
    // agg3: Q3 = d*sum(P2)                B -> A
    k_agg<64, false, false, false, false><<<AGGBLK, 256>>>(nullptr);
    // L3: H3 = Q3@W3 + b3                 A -> B      (FIN=64,FOUT=128,BM=64,TN=8)
    k_gemm<64, 128, 64, 8, true, false, false, false, false>
        <<<(NNODES + 63) / 64, 256>>>(nullptr, W3, b3);

    // Pool + MLP head
    k_pool<<<(NNODES + 127) / 128, 128>>>(batch);
    k_mlp<<<NGRAPH, 128>>>(Wl1, bl1, Wl2, bl2, out);
}

// round 5
// speedup vs baseline: 1.9791x; 1.2620x over previous
#include <cuda_runtime.h>
#include <math.h>

// Problem-fixed shapes
#define NNODES 100000
#define NEDGES 1600000
#define NGRAPH 512

// ---------------- scratch (device globals; no allocation) ----------------
__device__ int   d_deg[NNODES];
__device__ int   d_rowptr[NNODES + 1];
__device__ int   d_cursor[NNODES];
__device__ int   d_col[NEDGES];
__device__ float d_dinv[NNODES];
__device__ float d_bufA[(size_t)NNODES * 64];
__device__ float d_bufB[(size_t)NNODES * 64];
__device__ float d_g64[NGRAPH * 64];
__device__ int   d_cnt[NGRAPH];
__device__ int   d_bsum[256];

// ---------------- zero + CSR build ----------------
__global__ void k_zero() {
    int i = blockIdx.x * blockDim.x + threadIdx.x;
    if (i < NNODES) d_deg[i] = 0;
    if (i < NGRAPH * 64) d_g64[i] = 0.f;
    if (i < NGRAPH) d_cnt[i] = 0;
}

__global__ void k_deg(const int4* __restrict__ dst4) {
    int e = blockIdx.x * blockDim.x + threadIdx.x;
    if (e < NEDGES / 4) {
        int4 d = dst4[e];
        atomicAdd(&d_deg[d.x], 1);
        atomicAdd(&d_deg[d.y], 1);
        atomicAdd(&d_deg[d.z], 1);
        atomicAdd(&d_deg[d.w], 1);
    }
}

// block-local exclusive scan (512 elems per block)
__global__ void k_scan1() {
    __shared__ int s[512];
    int i = blockIdx.x * 512 + threadIdx.x;
    int v = (i < NNODES) ? d_deg[i] : 0;
    s[threadIdx.x] = v;
    __syncthreads();
    for (int off = 1; off < 512; off <<= 1) {
        int t = (threadIdx.x >= off) ? s[threadIdx.x - off] : 0;
        __syncthreads();
        s[threadIdx.x] += t;
        __syncthreads();
    }
    if (i < NNODES) d_rowptr[i] = s[threadIdx.x] - v;  // exclusive within block
    if (threadIdx.x == 511) d_bsum[blockIdx.x] = s[511];
}

// parallel exclusive scan over block sums (nblk <= 256)
__global__ void k_scan2(int nblk) {
    __shared__ int s[256];
    int t = threadIdx.x;
    int v = (t < nblk) ? d_bsum[t] : 0;
    s[t] = v;
    __syncthreads();
    for (int off = 1; off < 256; off <<= 1) {
        int u = (t >= off) ? s[t - off] : 0;
        __syncthreads();
        s[t] += u;
        __syncthreads();
    }
    if (t < nblk) d_bsum[t] = s[t] - v;  // exclusive
    if (t == nblk - 1) d_rowptr[NNODES] = s[t];
}

__global__ void k_scan3() {
    int i = blockIdx.x * 512 + threadIdx.x;
    if (i < NNODES) {
        int r = d_rowptr[i] + d_bsum[blockIdx.x];
        d_rowptr[i] = r;
        d_cursor[i] = r;
        d_dinv[i] = rsqrtf((float)(d_deg[i] + 1));  // +1 = self loop
    }
}

__global__ void k_scatter(const int4* __restrict__ src4,
                          const int4* __restrict__ dst4) {
    int e = blockIdx.x * blockDim.x + threadIdx.x;
    if (e < NEDGES / 4) {
        int4 s = src4[e];
        int4 d = dst4[e];
        d_col[atomicAdd(&d_cursor[d.x], 1)] = s.x;
        d_col[atomicAdd(&d_cursor[d.y], 1)] = s.y;
        d_col[atomicAdd(&d_cursor[d.z], 1)] = s.z;
        d_col[atomicAdd(&d_cursor[d.w], 1)] = s.w;
    }
}

// ---------------- register-tiled GEMM ----------------
// Y = epilogue(H @ W).  H:[n,FIN] row-major (SRC_EXT ? Hext : d_bufA),
// Y:[n,FOUT] (DST_A ? d_bufA : d_bufB).
// Thread tile 4 x TN. Block tile BM x FOUT. 256 threads.
template <int FIN, int FOUT, int BM, int TN,
          bool BIAS, bool RELU, bool OUTD, bool SRC_EXT, bool DST_A>
__launch_bounds__(256)
__global__ void k_gemm(const float* __restrict__ Hext,
                       const float* __restrict__ W,
                       const float* __restrict__ bias) {
    const float* __restrict__ H = SRC_EXT ? Hext : (const float*)d_bufA;
    float* __restrict__ Y = DST_A ? d_bufA : d_bufB;

    constexpr int KT = 32;
    __shared__ float Ws[FIN][FOUT];
    __shared__ float As[KT][BM + 4];

    for (int i = threadIdx.x; i < FIN * FOUT; i += 256)
        ((float*)Ws)[i] = W[i];

    constexpr int CG = FOUT / TN;
    constexpr int RG = BM / 4;
    static_assert(CG * RG == 256, "tiling");
    const int tc = threadIdx.x % CG;
    const int tr = threadIdx.x / CG;
    const int row0 = blockIdx.x * BM;

    float acc[4][TN];
#pragma unroll
    for (int m = 0; m < 4; m++)
#pragma unroll
        for (int n = 0; n < TN; n++) acc[m][n] = 0.f;

    for (int k0 = 0; k0 < FIN; k0 += KT) {
        __syncthreads();
        constexpr int LOADS = BM * KT / 4;
        for (int i = threadIdx.x; i < LOADS; i += 256) {
            int r = i / (KT / 4);
            int kc = (i % (KT / 4)) * 4;
            int gr = row0 + r;
            float4 v = (gr < NNODES)
                ? *reinterpret_cast<const float4*>(&H[(size_t)gr * FIN + k0 + kc])
                : make_float4(0.f, 0.f, 0.f, 0.f);
            As[kc + 0][r] = v.x;
            As[kc + 1][r] = v.y;
            As[kc + 2][r] = v.z;
            As[kc + 3][r] = v.w;
        }
        __syncthreads();
#pragma unroll
        for (int k = 0; k < KT; k++) {
            float a[4];
            const float4 av = *reinterpret_cast<const float4*>(&As[k][tr * 4]);
            a[0] = av.x; a[1] = av.y; a[2] = av.z; a[3] = av.w;
            float w[TN];
#pragma unroll
            for (int n = 0; n < TN; n += 4) {
                const float4 wv = *reinterpret_cast<const float4*>(&Ws[k0 + k][tc * TN + n]);
                w[n + 0] = wv.x; w[n + 1] = wv.y; w[n + 2] = wv.z; w[n + 3] = wv.w;
            }
#pragma unroll
            for (int m = 0; m < 4; m++)
#pragma unroll
                for (int n = 0; n < TN; n++)
                    acc[m][n] += a[m] * w[n];
        }
    }

    float b[TN];
    if (BIAS) {
#pragma unroll
        for (int n = 0; n < TN; n++) b[n] = bias[tc * TN + n];
    }
#pragma unroll
    for (int m = 0; m < 4; m++) {
        int row = row0 + tr * 4 + m;
        if (row < NNODES) {
            float d = OUTD ? d_dinv[row] : 1.f;
#pragma unroll
            for (int n = 0; n < TN; n += 4) {
                float4 v;
                float t0 = acc[m][n + 0], t1 = acc[m][n + 1],
                      t2 = acc[m][n + 2], t3 = acc[m][n + 3];
                if (BIAS) { t0 += b[n]; t1 += b[n + 1]; t2 += b[n + 2]; t3 += b[n + 3]; }
                if (RELU) { t0 = fmaxf(t0, 0.f); t1 = fmaxf(t1, 0.f);
                            t2 = fmaxf(t2, 0.f); t3 = fmaxf(t3, 0.f); }
                if (OUTD) { t0 *= d; t1 *= d; t2 *= d; t3 *= d; }
                v.x = t0; v.y = t1; v.z = t2; v.w = t3;
                *reinterpret_cast<float4*>(&Y[(size_t)row * FOUT + tc * TN + n]) = v;
            }
        }
    }
}

// ---------------- sparse aggregation (gather, warp per node) ----------------
template <int F, bool A_SRC, bool BIAS, bool RELU, bool POSTD>
__launch_bounds__(256)
__global__ void k_agg(const float* __restrict__ bias) {
    const float* __restrict__ Y = A_SRC ? (const float*)d_bufA : (const float*)d_bufB;
    float* __restrict__ O = A_SRC ? d_bufB : d_bufA;

    int warp = (blockIdx.x * 256 + threadIdx.x) >> 5;
    if (warp >= NNODES) return;
    int lane = threadIdx.x & 31;
    constexpr int V = F / 32;
    float acc[V];

    const float* pself = Y + (size_t)warp * F + lane * V;
    if constexpr (V == 2) {
        float2 t = *reinterpret_cast<const float2*>(pself);
        acc[0] = t.x; acc[1] = t.y;
    } else {
        acc[0] = *pself;
    }

    int s = __ldg(&d_rowptr[warp]);
    int e = __ldg(&d_rowptr[warp + 1]);
#pragma unroll 4
    for (int j = s; j < e; j++) {
        int c = __ldg(&d_col[j]);
        const float* p = Y + (size_t)c * F + lane * V;
        if constexpr (V == 2) {
            float2 t = *reinterpret_cast<const float2*>(p);
            acc[0] += t.x; acc[1] += t.y;
        } else {
            acc[0] += *p;
        }
    }

    float d = d_dinv[warp];
    float o[V];
#pragma unroll
    for (int v = 0; v < V; v++) {
        float t = d * acc[v];
        if (BIAS) t += bias[lane * V + v];
        if (RELU) t = fmaxf(t, 0.f);
        if (POSTD) t *= d;
        o[v] = t;
    }
    if constexpr (V == 2) {
        *reinterpret_cast<float2*>(&O[(size_t)warp * F + lane * 2]) = make_float2(o[0], o[1]);
    } else {
        O[(size_t)warp * F + lane] = o[0];
    }
}

// ---------------- pooling at F=64 + per-graph node counts ----------------
// reads d_bufA (agg3 output, = N H2), writes d_g64 and d_cnt.
__global__ void k_pool64(const int* __restrict__ batch) {
    const float* __restrict__ H = d_bufA;
    int i0 = blockIdx.x * 128;
    if (i0 >= NNODES) return;
    int i1 = min(i0 + 128, NNODES);
    int f = threadIdx.x;  // 0..63
    int cur = batch[i0];
    float acc = 0.f;
    int run = 0;
    for (int i = i0; i < i1; i++) {
        int b = batch[i];
        if (b != cur) {
            atomicAdd(&d_g64[cur * 64 + f], acc);
            if (f == 0) atomicAdd(&d_cnt[cur], run);
            acc = 0.f; run = 0;
            cur = b;
        }
        acc += H[(size_t)i * 64 + f];
        run++;
    }
    atomicAdd(&d_g64[cur * 64 + f], acc);
    if (f == 0) atomicAdd(&d_cnt[cur], run);
}

// ---------------- GEMM3 (folded, tiny) + MLP head + log_softmax ----------------
// h3 = g64 @ W3 + cnt*b3 ; hid = relu(h3@Wl1+bl1) ; o = hid@Wl2+bl2 ; log_softmax
__global__ void k_mlp(const float* __restrict__ W3, const float* __restrict__ b3,
                      const float* __restrict__ Wl1, const float* __restrict__ bl1,
                      const float* __restrict__ Wl2, const float* __restrict__ bl2,
                      float* __restrict__ out) {
    __shared__ float g[64];
    __shared__ float h3[128];
    __shared__ float hid[64];
    __shared__ float o[10];
    int b = blockIdx.x, t = threadIdx.x;
    if (t < 64) g[t] = d_g64[b * 64 + t];
    __syncthreads();
    float nb = (float)d_cnt[b];
    {   // h3[t], t in 0..127
        float a = nb * b3[t];
        for (int k = 0; k < 64; k++) a += g[k] * W3[k * 128 + t];
        h3[t] = a;
    }
    __syncthreads();
    if (t < 64) {
        float a = bl1[t];
        for (int k = 0; k < 128; k++) a += h3[k] * Wl1[k * 64 + t];
        hid[t] = fmaxf(a, 0.f);
    }
    __syncthreads();
    if (t < 10) {
        float a = bl2[t];
        for (int k = 0; k < 64; k++) a += hid[k] * Wl2[k * 10 + t];
        o[t] = a;
    }
    __syncthreads();
    if (t == 0) {
        float m = -INFINITY;
        for (int i = 0; i < 10; i++) m = fmaxf(m, o[i]);
        float s = 0.f;
        for (int i = 0; i < 10; i++) s += expf(o[i] - m);
        float l = m + logf(s);
        for (int i = 0; i < 10; i++) out[b * 10 + i] = o[i] - l;
    }
}

// ---------------- launch ----------------
extern "C" void kernel_launch(void* const* d_in, const int* in_sizes, int n_in,
                              void* d_out, int out_size) {
    const float* x     = (const float*)d_in[0];
    const int*   ei    = (const int*)d_in[1];   // [2, E] int32
    const int*   batch = (const int*)d_in[2];   // int32
    const float* W1  = (const float*)d_in[3];
    const float* b1  = (const float*)d_in[4];
    const float* W2  = (const float*)d_in[5];
    const float* b2  = (const float*)d_in[6];
    const float* W3  = (const float*)d_in[7];
    const float* b3  = (const float*)d_in[8];
    const float* Wl1 = (const float*)d_in[9];
    const float* bl1 = (const float*)d_in[10];
    const float* Wl2 = (const float*)d_in[11];
    const float* bl2 = (const float*)d_in[12];
    float* out = (float*)d_out;

    const int4* src4 = (const int4*)ei;
    const int4* dst4 = (const int4*)(ei + NEDGES);

    const int NBLK_SCAN = (NNODES + 511) / 512;  // 196
    const int E4BLK = (NEDGES / 4 + 255) / 256;  // 1563
    const int AGGBLK = (NNODES * 32 + 255) / 256;

    // zero + CSR build + dinv
    k_zero<<<(NNODES + 255) / 256, 256>>>();
    k_deg<<<E4BLK, 256>>>(dst4);
    k_scan1<<<NBLK_SCAN, 512>>>();
    k_scan2<<<1, 256>>>(NBLK_SCAN);
    k_scan3<<<NBLK_SCAN, 512>>>();
    k_scatter<<<E4BLK, 256>>>(src4, dst4);

    // L1: Y1 = d*(x@W1)                  x -> A      (128->32)
    k_gemm<128, 32, 128, 4, false, false, true, true, true>
        <<<(NNODES + 127) / 128, 256>>>(x, W1, nullptr);
    // agg1: P1 = d*relu(d*sum + b1)      A -> B      (F=32)
    k_agg<32, true, true, true, true><<<AGGBLK, 256>>>(b1);
    // agg2: Q2 = d*sum(P1)               B -> A      (F=32)
    k_agg<32, false, false, false, false><<<AGGBLK, 256>>>(nullptr);
    // L2: P2 = d*relu(Q2@W2 + b2)        A -> B      (32->64)
    k_gemm<32, 64, 64, 4, true, true, true, false, false>
        <<<(NNODES + 63) / 64, 256>>>(nullptr, W2, b2);
    // agg3: Q3 = d*sum(P2)               B -> A      (F=64)
    k_agg<64, false, false, false, false><<<AGGBLK, 256>>>(nullptr);

    // pool at F=64 (+ node counts), then folded GEMM3 + MLP head
    k_pool64<<<(NNODES + 127) / 128, 64>>>(batch);
    k_mlp<<<NGRAPH, 128>>>(W3, b3, Wl1, bl1, Wl2, bl2, out);
}

// round 6
// speedup vs baseline: 2.1717x; 1.0973x over previous
#include <cuda_runtime.h>
#include <math.h>

// Problem-fixed shapes
#define NNODES 100000
#define NEDGES 1600000
#define NGRAPH 512

// ---------------- scratch (device globals; no allocation) ----------------
__device__ int   d_deg[NNODES];
__device__ int   d_rowptr[NNODES + 1];
__device__ int   d_cursor[NNODES];
__device__ int   d_col[NEDGES];
__device__ float d_dinv[NNODES];
__device__ float d_bufA[(size_t)NNODES * 64];
__device__ float d_bufB[(size_t)NNODES * 64];
__device__ float d_g64[NGRAPH * 64];
__device__ int   d_cnt[NGRAPH];
__device__ int   d_bsum[256];

// ---------------- zero + CSR build ----------------
__global__ void k_zero() {
    int i = blockIdx.x * blockDim.x + threadIdx.x;
    if (i < NNODES) d_deg[i] = 0;
    if (i < NGRAPH * 64) d_g64[i] = 0.f;
    if (i < NGRAPH) d_cnt[i] = 0;
}

__global__ void k_deg(const int4* __restrict__ dst4) {
    int e = blockIdx.x * blockDim.x + threadIdx.x;
    if (e < NEDGES / 4) {
        int4 d = dst4[e];
        atomicAdd(&d_deg[d.x], 1);
        atomicAdd(&d_deg[d.y], 1);
        atomicAdd(&d_deg[d.z], 1);
        atomicAdd(&d_deg[d.w], 1);
    }
}

// block-local exclusive scan (512 elems per block)
__global__ void k_scan1() {
    __shared__ int s[512];
    int i = blockIdx.x * 512 + threadIdx.x;
    int v = (i < NNODES) ? d_deg[i] : 0;
    s[threadIdx.x] = v;
    __syncthreads();
    for (int off = 1; off < 512; off <<= 1) {
        int t = (threadIdx.x >= off) ? s[threadIdx.x - off] : 0;
        __syncthreads();
        s[threadIdx.x] += t;
        __syncthreads();
    }
    if (i < NNODES) d_rowptr[i] = s[threadIdx.x] - v;  // exclusive within block
    if (threadIdx.x == 511) d_bsum[blockIdx.x] = s[511];
}

// parallel exclusive scan over block sums (nblk <= 256)
__global__ void k_scan2(int nblk) {
    __shared__ int s[256];
    int t = threadIdx.x;
    int v = (t < nblk) ? d_bsum[t] : 0;
    s[t] = v;
    __syncthreads();
    for (int off = 1; off < 256; off <<= 1) {
        int u = (t >= off) ? s[t - off] : 0;
        __syncthreads();
        s[t] += u;
        __syncthreads();
    }
    if (t < nblk) d_bsum[t] = s[t] - v;  // exclusive
    if (t == nblk - 1) d_rowptr[NNODES] = s[t];
}

__global__ void k_scan3() {
    int i = blockIdx.x * 512 + threadIdx.x;
    if (i < NNODES) {
        int r = d_rowptr[i] + d_bsum[blockIdx.x];
        d_rowptr[i] = r;
        d_cursor[i] = r;
        d_dinv[i] = rsqrtf((float)(d_deg[i] + 1));  // +1 = self loop
    }
}

__global__ void k_scatter(const int4* __restrict__ src4,
                          const int4* __restrict__ dst4) {
    int e = blockIdx.x * blockDim.x + threadIdx.x;
    if (e < NEDGES / 4) {
        int4 s = src4[e];
        int4 d = dst4[e];
        d_col[atomicAdd(&d_cursor[d.x], 1)] = s.x;
        d_col[atomicAdd(&d_cursor[d.y], 1)] = s.y;
        d_col[atomicAdd(&d_cursor[d.z], 1)] = s.z;
        d_col[atomicAdd(&d_cursor[d.w], 1)] = s.w;
    }
}

// ---------------- register-tiled GEMM ----------------
// Y = epilogue(H @ W).  H:[n,FIN] row-major (SRC_EXT ? Hext : d_bufA),
// Y:[n,FOUT] (DST_A ? d_bufA : d_bufB).
template <int FIN, int FOUT, int BM, int TN,
          bool BIAS, bool RELU, bool OUTD, bool SRC_EXT, bool DST_A>
__launch_bounds__(256)
__global__ void k_gemm(const float* __restrict__ Hext,
                       const float* __restrict__ W,
                       const float* __restrict__ bias) {
    const float* __restrict__ H = SRC_EXT ? Hext : (const float*)d_bufA;
    float* __restrict__ Y = DST_A ? d_bufA : d_bufB;

    constexpr int KT = 32;
    __shared__ float Ws[FIN][FOUT];
    __shared__ float As[KT][BM + 4];

    for (int i = threadIdx.x; i < FIN * FOUT; i += 256)
        ((float*)Ws)[i] = W[i];

    constexpr int CG = FOUT / TN;
    constexpr int RG = BM / 4;
    static_assert(CG * RG == 256, "tiling");
    const int tc = threadIdx.x % CG;
    const int tr = threadIdx.x / CG;
    const int row0 = blockIdx.x * BM;

    float acc[4][TN];
#pragma unroll
    for (int m = 0; m < 4; m++)
#pragma unroll
        for (int n = 0; n < TN; n++) acc[m][n] = 0.f;

    for (int k0 = 0; k0 < FIN; k0 += KT) {
        __syncthreads();
        constexpr int LOADS = BM * KT / 4;
        for (int i = threadIdx.x; i < LOADS; i += 256) {
            int r = i / (KT / 4);
            int kc = (i % (KT / 4)) * 4;
            int gr = row0 + r;
            float4 v = (gr < NNODES)
                ? *reinterpret_cast<const float4*>(&H[(size_t)gr * FIN + k0 + kc])
                : make_float4(0.f, 0.f, 0.f, 0.f);
            As[kc + 0][r] = v.x;
            As[kc + 1][r] = v.y;
            As[kc + 2][r] = v.z;
            As[kc + 3][r] = v.w;
        }
        __syncthreads();
#pragma unroll
        for (int k = 0; k < KT; k++) {
            float a[4];
            const float4 av = *reinterpret_cast<const float4*>(&As[k][tr * 4]);
            a[0] = av.x; a[1] = av.y; a[2] = av.z; a[3] = av.w;
            float w[TN];
#pragma unroll
            for (int n = 0; n < TN; n += 4) {
                const float4 wv = *reinterpret_cast<const float4*>(&Ws[k0 + k][tc * TN + n]);
                w[n + 0] = wv.x; w[n + 1] = wv.y; w[n + 2] = wv.z; w[n + 3] = wv.w;
            }
#pragma unroll
            for (int m = 0; m < 4; m++)
#pragma unroll
                for (int n = 0; n < TN; n++)
                    acc[m][n] += a[m] * w[n];
        }
    }

    float b[TN];
    if (BIAS) {
#pragma unroll
        for (int n = 0; n < TN; n++) b[n] = bias[tc * TN + n];
    }
#pragma unroll
    for (int m = 0; m < 4; m++) {
        int row = row0 + tr * 4 + m;
        if (row < NNODES) {
            float d = OUTD ? d_dinv[row] : 1.f;
#pragma unroll
            for (int n = 0; n < TN; n += 4) {
                float4 v;
                float t0 = acc[m][n + 0], t1 = acc[m][n + 1],
                      t2 = acc[m][n + 2], t3 = acc[m][n + 3];
                if (BIAS) { t0 += b[n]; t1 += b[n + 1]; t2 += b[n + 2]; t3 += b[n + 3]; }
                if (RELU) { t0 = fmaxf(t0, 0.f); t1 = fmaxf(t1, 0.f);
                            t2 = fmaxf(t2, 0.f); t3 = fmaxf(t3, 0.f); }
                if (OUTD) { t0 *= d; t1 *= d; t2 *= d; t3 *= d; }
                v.x = t0; v.y = t1; v.z = t2; v.w = t3;
                *reinterpret_cast<float4*>(&Y[(size_t)row * FOUT + tc * TN + n]) = v;
            }
        }
    }
}

// ---------------- sparse aggregation: multi-node-per-warp float4 gather ----
// L = F/4 lanes per node, G = 32/L nodes per warp.
// acc = self + sum_{j->node} SRC[col[j]]; epilogue as flags.
template <int F, bool A_SRC, bool BIAS, bool RELU, bool POSTD>
__launch_bounds__(256)
__global__ void k_agg(const float* __restrict__ bias) {
    const float4* __restrict__ Y = A_SRC ? (const float4*)d_bufA : (const float4*)d_bufB;
    float4* __restrict__ O = A_SRC ? (float4*)d_bufB : (float4*)d_bufA;

    constexpr int L = F / 4;   // lanes per node
    constexpr int G = 32 / L;  // nodes per warp
    constexpr int FV = F / 4;  // float4 per row

    int warp = (blockIdx.x * 256 + threadIdx.x) >> 5;
    int lane = threadIdx.x & 31;
    int g = lane / L;
    int fl = lane % L;
    int node = warp * G + g;
    if (node >= NNODES) return;

    float4 acc = __ldg(&Y[(size_t)node * FV + fl]);  // self contribution

    int s = __ldg(&d_rowptr[node]);
    int e = __ldg(&d_rowptr[node + 1]);
#pragma unroll 2
    for (int j = s; j < e; j++) {
        int c = __ldg(&d_col[j]);
        float4 t = __ldg(&Y[(size_t)c * FV + fl]);
        acc.x += t.x; acc.y += t.y; acc.z += t.z; acc.w += t.w;
    }

    float d = d_dinv[node];
    acc.x *= d; acc.y *= d; acc.z *= d; acc.w *= d;
    if (BIAS) {
        float4 b = *reinterpret_cast<const float4*>(&bias[fl * 4]);
        acc.x += b.x; acc.y += b.y; acc.z += b.z; acc.w += b.w;
    }
    if (RELU) {
        acc.x = fmaxf(acc.x, 0.f); acc.y = fmaxf(acc.y, 0.f);
        acc.z = fmaxf(acc.z, 0.f); acc.w = fmaxf(acc.w, 0.f);
    }
    if (POSTD) {
        acc.x *= d; acc.y *= d; acc.z *= d; acc.w *= d;
    }
    O[(size_t)node * FV + fl] = acc;
}

// ---------------- pooling at F=64 + per-graph node counts ----------------
__global__ void k_pool64(const int* __restrict__ batch) {
    const float* __restrict__ H = d_bufA;
    int i0 = blockIdx.x * 128;
    if (i0 >= NNODES) return;
    int i1 = min(i0 + 128, NNODES);
    int f = threadIdx.x;  // 0..63
    int cur = batch[i0];
    float acc = 0.f;
    int run = 0;
    for (int i = i0; i < i1; i++) {
        int b = batch[i];
        if (b != cur) {
            atomicAdd(&d_g64[cur * 64 + f], acc);
            if (f == 0) atomicAdd(&d_cnt[cur], run);
            acc = 0.f; run = 0;
            cur = b;
        }
        acc += H[(size_t)i * 64 + f];
        run++;
    }
    atomicAdd(&d_g64[cur * 64 + f], acc);
    if (f == 0) atomicAdd(&d_cnt[cur], run);
}

// ---------------- GEMM3 (folded, tiny) + MLP head + log_softmax ----------------
__global__ void k_mlp(const float* __restrict__ W3, const float* __restrict__ b3,
                      const float* __restrict__ Wl1, const float* __restrict__ bl1,
                      const float* __restrict__ Wl2, const float* __restrict__ bl2,
                      float* __restrict__ out) {
    __shared__ float g[64];
    __shared__ float h3[128];
    __shared__ float hid[64];
    __shared__ float o[10];
    int b = blockIdx.x, t = threadIdx.x;
    if (t < 64) g[t] = d_g64[b * 64 + t];
    __syncthreads();
    float nb = (float)d_cnt[b];
    {
        float a = nb * b3[t];
        for (int k = 0; k < 64; k++) a += g[k] * W3[k * 128 + t];
        h3[t] = a;
    }
    __syncthreads();
    if (t < 64) {
        float a = bl1[t];
        for (int k = 0; k < 128; k++) a += h3[k] * Wl1[k * 64 + t];
        hid[t] = fmaxf(a, 0.f);
    }
    __syncthreads();
    if (t < 10) {
        float a = bl2[t];
        for (int k = 0; k < 64; k++) a += hid[k] * Wl2[k * 10 + t];
        o[t] = a;
    }
    __syncthreads();
    if (t == 0) {
        float m = -INFINITY;
        for (int i = 0; i < 10; i++) m = fmaxf(m, o[i]);
        float s = 0.f;
        for (int i = 0; i < 10; i++) s += expf(o[i] - m);
        float l = m + logf(s);
        for (int i = 0; i < 10; i++) out[b * 10 + i] = o[i] - l;
    }
}

// ---------------- launch ----------------
extern "C" void kernel_launch(void* const* d_in, const int* in_sizes, int n_in,
                              void* d_out, int out_size) {
    const float* x     = (const float*)d_in[0];
    const int*   ei    = (const int*)d_in[1];
    const int*   batch = (const int*)d_in[2];
    const float* W1  = (const float*)d_in[3];
    const float* b1  = (const float*)d_in[4];
    const float* W2  = (const float*)d_in[5];
    const float* b2  = (const float*)d_in[6];
    const float* W3  = (const float*)d_in[7];
    const float* b3  = (const float*)d_in[8];
    const float* Wl1 = (const float*)d_in[9];
    const float* bl1 = (const float*)d_in[10];
    const float* Wl2 = (const float*)d_in[11];
    const float* bl2 = (const float*)d_in[12];
    float* out = (float*)d_out;

    const int4* src4 = (const int4*)ei;
    const int4* dst4 = (const int4*)(ei + NEDGES);

    const int NBLK_SCAN = (NNODES + 511) / 512;  // 196
    const int E4BLK = (NEDGES / 4 + 255) / 256;  // 1563

    // warps needed: F=32 -> 4 nodes/warp, F=64 -> 2 nodes/warp
    const int AGG32_BLK = ((NNODES + 3) / 4 * 32 + 255) / 256;   // 3125
    const int AGG64_BLK = ((NNODES + 1) / 2 * 32 + 255) / 256;   // 6250

    // zero + CSR build + dinv
    k_zero<<<(NNODES + 255) / 256, 256>>>();
    k_deg<<<E4BLK, 256>>>(dst4);
    k_scan1<<<NBLK_SCAN, 512>>>();
    k_scan2<<<1, 256>>>(NBLK_SCAN);
    k_scan3<<<NBLK_SCAN, 512>>>();
    k_scatter<<<E4BLK, 256>>>(src4, dst4);

    // L1: Y1 = d*(x@W1)                  x -> A      (128->32)
    k_gemm<128, 32, 128, 4, false, false, true, true, true>
        <<<(NNODES + 127) / 128, 256>>>(x, W1, nullptr);
    // agg1: P1 = d*relu(d*sum + b1)      A -> B      (F=32)
    k_agg<32, true, true, true, true><<<AGG32_BLK, 256>>>(b1);
    // agg2: Q2 = d*sum(P1)               B -> A      (F=32)
    k_agg<32, false, false, false, false><<<AGG32_BLK, 256>>>(nullptr);
    // L2: P2 = d*relu(Q2@W2 + b2)        A -> B      (32->64)
    k_gemm<32, 64, 64, 4, true, true, true, false, false>
        <<<(NNODES + 63) / 64, 256>>>(nullptr, W2, b2);
    // agg3: Q3 = d*sum(P2)               B -> A      (F=64)
    k_agg<64, false, false, false, false><<<AGG64_BLK, 256>>>(nullptr);

    // pool at F=64 (+ node counts), then folded GEMM3 + MLP head
    k_pool64<<<(NNODES + 127) / 128, 64>>>(batch);
    k_mlp<<<NGRAPH, 128>>>(W3, b3, Wl1, bl1, Wl2, bl2, out);
}

// round 7
// speedup vs baseline: 2.4460x; 1.1263x over previous
#include <cuda_runtime.h>
#include <cuda_fp16.h>
#include <math.h>

// Problem-fixed shapes
#define NNODES 100000
#define NEDGES 1600000
#define NGRAPH 512

// ---------------- scratch (device globals; no allocation) ----------------
__device__ int    d_deg[NNODES];
__device__ int    d_rowptr[NNODES + 1];
__device__ int    d_cursor[NNODES];
__device__ int    d_col[NEDGES];
__device__ float  d_dinv[NNODES];
__device__ __half d_hA[(size_t)NNODES * 64];
__device__ __half d_hB[(size_t)NNODES * 64];
__device__ float  d_g64[NGRAPH * 64];
__device__ int    d_cnt[NGRAPH];
__device__ int    d_bsum[256];

// ---------------- zero + CSR build ----------------
__global__ void k_zero() {
    int i = blockIdx.x * blockDim.x + threadIdx.x;
    if (i < NNODES) d_deg[i] = 0;
    if (i < NGRAPH * 64) d_g64[i] = 0.f;
    if (i < NGRAPH) d_cnt[i] = 0;
}

__global__ void k_deg(const int4* __restrict__ dst4) {
    int e = blockIdx.x * blockDim.x + threadIdx.x;
    if (e < NEDGES / 4) {
        int4 d = dst4[e];
        atomicAdd(&d_deg[d.x], 1);
        atomicAdd(&d_deg[d.y], 1);
        atomicAdd(&d_deg[d.z], 1);
        atomicAdd(&d_deg[d.w], 1);
    }
}

// block-local exclusive scan (512 elems per block)
__global__ void k_scan1() {
    __shared__ int s[512];
    int i = blockIdx.x * 512 + threadIdx.x;
    int v = (i < NNODES) ? d_deg[i] : 0;
    s[threadIdx.x] = v;
    __syncthreads();
    for (int off = 1; off < 512; off <<= 1) {
        int t = (threadIdx.x >= off) ? s[threadIdx.x - off] : 0;
        __syncthreads();
        s[threadIdx.x] += t;
        __syncthreads();
    }
    if (i < NNODES) d_rowptr[i] = s[threadIdx.x] - v;
    if (threadIdx.x == 511) d_bsum[blockIdx.x] = s[511];
}

// parallel exclusive scan over block sums (nblk <= 256)
__global__ void k_scan2(int nblk) {
    __shared__ int s[256];
    int t = threadIdx.x;
    int v = (t < nblk) ? d_bsum[t] : 0;
    s[t] = v;
    __syncthreads();
    for (int off = 1; off < 256; off <<= 1) {
        int u = (t >= off) ? s[t - off] : 0;
        __syncthreads();
        s[t] += u;
        __syncthreads();
    }
    if (t < nblk) d_bsum[t] = s[t] - v;
    if (t == nblk - 1) d_rowptr[NNODES] = s[t];
}

__global__ void k_scan3() {
    int i = blockIdx.x * 512 + threadIdx.x;
    if (i < NNODES) {
        int r = d_rowptr[i] + d_bsum[blockIdx.x];
        d_rowptr[i] = r;
        d_cursor[i] = r;
        d_dinv[i] = rsqrtf((float)(d_deg[i] + 1));
    }
}

__global__ void k_scatter(const int4* __restrict__ src4,
                          const int4* __restrict__ dst4) {
    int e = blockIdx.x * blockDim.x + threadIdx.x;
    if (e < NEDGES / 4) {
        int4 s = src4[e];
        int4 d = dst4[e];
        d_col[atomicAdd(&d_cursor[d.x], 1)] = s.x;
        d_col[atomicAdd(&d_cursor[d.y], 1)] = s.y;
        d_col[atomicAdd(&d_cursor[d.z], 1)] = s.z;
        d_col[atomicAdd(&d_cursor[d.w], 1)] = s.w;
    }
}

// ---------------- register-tiled GEMM, fp16 output ----------------
// Y = epilogue(H @ W), Y stored as half in (DST_A ? d_hA : d_hB).
// H: fp32 external (IN_HALF=false) or half d_hA (IN_HALF=true).
template <int FIN, int FOUT, int BM, int TN,
          bool BIAS, bool RELU, bool OUTD, bool IN_HALF, bool DST_A>
__launch_bounds__(256)
__global__ void k_gemm(const float* __restrict__ Hext,
                       const float* __restrict__ W,
                       const float* __restrict__ bias) {
    const float*  __restrict__ Hf = Hext;
    const __half* __restrict__ Hh = (const __half*)d_hA;
    __half* __restrict__ Y = DST_A ? d_hA : d_hB;

    constexpr int KT = 32;
    __shared__ float Ws[FIN][FOUT];
    __shared__ float As[KT][BM + 4];

    for (int i = threadIdx.x; i < FIN * FOUT; i += 256)
        ((float*)Ws)[i] = W[i];

    constexpr int CG = FOUT / TN;
    constexpr int RG = BM / 4;
    static_assert(CG * RG == 256, "tiling");
    const int tc = threadIdx.x % CG;
    const int tr = threadIdx.x / CG;
    const int row0 = blockIdx.x * BM;

    float acc[4][TN];
#pragma unroll
    for (int m = 0; m < 4; m++)
#pragma unroll
        for (int n = 0; n < TN; n++) acc[m][n] = 0.f;

    for (int k0 = 0; k0 < FIN; k0 += KT) {
        __syncthreads();
        if (IN_HALF) {
            // 8 halves (16B) per load
            constexpr int LOADS = BM * KT / 8;
            for (int i = threadIdx.x; i < LOADS; i += 256) {
                int r = i / (KT / 8);
                int kc = (i % (KT / 8)) * 8;
                int gr = row0 + r;
                if (gr < NNODES) {
                    uint4 v = *reinterpret_cast<const uint4*>(&Hh[(size_t)gr * FIN + k0 + kc]);
                    const __half2* h = reinterpret_cast<const __half2*>(&v);
#pragma unroll
                    for (int q = 0; q < 4; q++) {
                        float2 f = __half22float2(h[q]);
                        As[kc + q * 2 + 0][r] = f.x;
                        As[kc + q * 2 + 1][r] = f.y;
                    }
                } else {
#pragma unroll
                    for (int q = 0; q < 8; q++) As[kc + q][r] = 0.f;
                }
            }
        } else {
            constexpr int LOADS = BM * KT / 4;
            for (int i = threadIdx.x; i < LOADS; i += 256) {
                int r = i / (KT / 4);
                int kc = (i % (KT / 4)) * 4;
                int gr = row0 + r;
                float4 v = (gr < NNODES)
                    ? *reinterpret_cast<const float4*>(&Hf[(size_t)gr * FIN + k0 + kc])
                    : make_float4(0.f, 0.f, 0.f, 0.f);
                As[kc + 0][r] = v.x;
                As[kc + 1][r] = v.y;
                As[kc + 2][r] = v.z;
                As[kc + 3][r] = v.w;
            }
        }
        __syncthreads();
#pragma unroll
        for (int k = 0; k < KT; k++) {
            float a[4];
            const float4 av = *reinterpret_cast<const float4*>(&As[k][tr * 4]);
            a[0] = av.x; a[1] = av.y; a[2] = av.z; a[3] = av.w;
            float w[TN];
#pragma unroll
            for (int n = 0; n < TN; n += 4) {
                const float4 wv = *reinterpret_cast<const float4*>(&Ws[k0 + k][tc * TN + n]);
                w[n + 0] = wv.x; w[n + 1] = wv.y; w[n + 2] = wv.z; w[n + 3] = wv.w;
            }
#pragma unroll
            for (int m = 0; m < 4; m++)
#pragma unroll
                for (int n = 0; n < TN; n++)
                    acc[m][n] += a[m] * w[n];
        }
    }

    float b[TN];
    if (BIAS) {
#pragma unroll
        for (int n = 0; n < TN; n++) b[n] = bias[tc * TN + n];
    }
#pragma unroll
    for (int m = 0; m < 4; m++) {
        int row = row0 + tr * 4 + m;
        if (row < NNODES) {
            float d = OUTD ? d_dinv[row] : 1.f;
            __half2 hv[TN / 2];
#pragma unroll
            for (int n = 0; n < TN; n += 2) {
                float t0 = acc[m][n + 0], t1 = acc[m][n + 1];
                if (BIAS) { t0 += b[n]; t1 += b[n + 1]; }
                if (RELU) { t0 = fmaxf(t0, 0.f); t1 = fmaxf(t1, 0.f); }
                if (OUTD) { t0 *= d; t1 *= d; }
                hv[n / 2] = __floats2half2_rn(t0, t1);
            }
            __half* dst = &Y[(size_t)row * FOUT + tc * TN];
            if (TN == 4) {
                *reinterpret_cast<uint2*>(dst) = *reinterpret_cast<uint2*>(hv);
            } else {
                *reinterpret_cast<uint4*>(dst) = *reinterpret_cast<uint4*>(hv);
            }
        }
    }
}

// ---------------- sparse aggregation: fp16 gather, fp32 accum ----------
// L = F/8 lanes per node (16B = 8 halves per lane), G = 32/L nodes per warp.
template <int F, bool A_SRC, bool BIAS, bool RELU, bool POSTD>
__launch_bounds__(256)
__global__ void k_agg(const float* __restrict__ bias) {
    const uint4* __restrict__ Y = A_SRC ? (const uint4*)d_hA : (const uint4*)d_hB;
    uint4* __restrict__ O = A_SRC ? (uint4*)d_hB : (uint4*)d_hA;

    constexpr int L = F / 8;   // lanes per node
    constexpr int G = 32 / L;  // nodes per warp
    constexpr int FV = F / 8;  // uint4 per row

    int warp = (blockIdx.x * 256 + threadIdx.x) >> 5;
    int lane = threadIdx.x & 31;
    int g = lane / L;
    int fl = lane % L;
    int node = warp * G + g;
    if (node >= NNODES) return;

    float acc[8];
    {
        uint4 v = __ldg(&Y[(size_t)node * FV + fl]);
        const __half2* h = reinterpret_cast<const __half2*>(&v);
#pragma unroll
        for (int q = 0; q < 4; q++) {
            float2 f = __half22float2(h[q]);
            acc[q * 2 + 0] = f.x;
            acc[q * 2 + 1] = f.y;
        }
    }

    int s = __ldg(&d_rowptr[node]);
    int e = __ldg(&d_rowptr[node + 1]);
#pragma unroll 2
    for (int j = s; j < e; j++) {
        int c = __ldg(&d_col[j]);
        uint4 v = __ldg(&Y[(size_t)c * FV + fl]);
        const __half2* h = reinterpret_cast<const __half2*>(&v);
#pragma unroll
        for (int q = 0; q < 4; q++) {
            float2 f = __half22float2(h[q]);
            acc[q * 2 + 0] += f.x;
            acc[q * 2 + 1] += f.y;
        }
    }

    float d = d_dinv[node];
    __half2 hv[4];
#pragma unroll
    for (int q = 0; q < 4; q++) {
        float t0 = acc[q * 2 + 0] * d;
        float t1 = acc[q * 2 + 1] * d;
        if (BIAS) { t0 += bias[fl * 8 + q * 2]; t1 += bias[fl * 8 + q * 2 + 1]; }
        if (RELU) { t0 = fmaxf(t0, 0.f); t1 = fmaxf(t1, 0.f); }
        if (POSTD) { t0 *= d; t1 *= d; }
        hv[q] = __floats2half2_rn(t0, t1);
    }
    O[(size_t)node * FV + fl] = *reinterpret_cast<uint4*>(hv);
}

// ---------------- pooling at F=64 (fp16 in, fp32 accum) ----------------
__global__ void k_pool64(const int* __restrict__ batch) {
    const __half* __restrict__ H = d_hA;
    int i0 = blockIdx.x * 128;
    if (i0 >= NNODES) return;
    int i1 = min(i0 + 128, NNODES);
    int f = threadIdx.x;  // 0..63
    int cur = batch[i0];
    float acc = 0.f;
    int run = 0;
    for (int i = i0; i < i1; i++) {
        int b = batch[i];
        if (b != cur) {
            atomicAdd(&d_g64[cur * 64 + f], acc);
            if (f == 0) atomicAdd(&d_cnt[cur], run);
            acc = 0.f; run = 0;
            cur = b;
        }
        acc += __half2float(H[(size_t)i * 64 + f]);
        run++;
    }
    atomicAdd(&d_g64[cur * 64 + f], acc);
    if (f == 0) atomicAdd(&d_cnt[cur], run);
}

// ---------------- GEMM3 (folded) + MLP head + log_softmax ----------------
__global__ void k_mlp(const float* __restrict__ W3, const float* __restrict__ b3,
                      const float* __restrict__ Wl1, const float* __restrict__ bl1,
                      const float* __restrict__ Wl2, const float* __restrict__ bl2,
                      float* __restrict__ out) {
    __shared__ float g[64];
    __shared__ float h3[128];
    __shared__ float hid[64];
    __shared__ float o[10];
    int b = blockIdx.x, t = threadIdx.x;
    if (t < 64) g[t] = d_g64[b * 64 + t];
    __syncthreads();
    float nb = (float)d_cnt[b];
    {
        float a = nb * b3[t];
        for (int k = 0; k < 64; k++) a += g[k] * W3[k * 128 + t];
        h3[t] = a;
    }
    __syncthreads();
    if (t < 64) {
        float a = bl1[t];
        for (int k = 0; k < 128; k++) a += h3[k] * Wl1[k * 64 + t];
        hid[t] = fmaxf(a, 0.f);
    }
    __syncthreads();
    if (t < 10) {
        float a = bl2[t];
        for (int k = 0; k < 64; k++) a += hid[k] * Wl2[k * 10 + t];
        o[t] = a;
    }
    __syncthreads();
    if (t == 0) {
        float m = -INFINITY;
        for (int i = 0; i < 10; i++) m = fmaxf(m, o[i]);
        float s = 0.f;
        for (int i = 0; i < 10; i++) s += expf(o[i] - m);
        float l = m + logf(s);
        for (int i = 0; i < 10; i++) out[b * 10 + i] = o[i] - l;
    }
}

// ---------------- launch ----------------
extern "C" void kernel_launch(void* const* d_in, const int* in_sizes, int n_in,
                              void* d_out, int out_size) {
    const float* x     = (const float*)d_in[0];
    const int*   ei    = (const int*)d_in[1];
    const int*   batch = (const int*)d_in[2];
    const float* W1  = (const float*)d_in[3];
    const float* b1  = (const float*)d_in[4];
    const float* W2  = (const float*)d_in[5];
    const float* b2  = (const float*)d_in[6];
    const float* W3  = (const float*)d_in[7];
    const float* b3  = (const float*)d_in[8];
    const float* Wl1 = (const float*)d_in[9];
    const float* bl1 = (const float*)d_in[10];
    const float* Wl2 = (const float*)d_in[11];
    const float* bl2 = (const float*)d_in[12];
    float* out = (float*)d_out;

    const int4* src4 = (const int4*)ei;
    const int4* dst4 = (const int4*)(ei + NEDGES);

    const int NBLK_SCAN = (NNODES + 511) / 512;  // 196
    const int E4BLK = (NEDGES / 4 + 255) / 256;  // 1563

    // F=32 -> 8 nodes/warp, F=64 -> 4 nodes/warp
    const int AGG32_BLK = ((NNODES + 7) / 8 * 32 + 255) / 256;   // 1563
    const int AGG64_BLK = ((NNODES + 3) / 4 * 32 + 255) / 256;   // 3125

    // zero + CSR build + dinv
    k_zero<<<(NNODES + 255) / 256, 256>>>();
    k_deg<<<E4BLK, 256>>>(dst4);
    k_scan1<<<NBLK_SCAN, 512>>>();
    k_scan2<<<1, 256>>>(NBLK_SCAN);
    k_scan3<<<NBLK_SCAN, 512>>>();
    k_scatter<<<E4BLK, 256>>>(src4, dst4);

    // L1: Y1 = d*(x@W1)                  x -> hA     (128->32, fp32 in)
    k_gemm<128, 32, 128, 4, false, false, true, false, true>
        <<<(NNODES + 127) / 128, 256>>>(x, W1, nullptr);
    // agg1: P1 = d*relu(d*sum + b1)      hA -> hB    (F=32)
    k_agg<32, true, true, true, true><<<AGG32_BLK, 256>>>(b1);
    // agg2: Q2 = d*sum(P1)               hB -> hA    (F=32)
    k_agg<32, false, false, false, false><<<AGG32_BLK, 256>>>(nullptr);
    // L2: P2 = d*relu(Q2@W2 + b2)        hA -> hB    (32->64, fp16 in)
    k_gemm<32, 64, 64, 4, true, true, true, true, false>
        <<<(NNODES + 63) / 64, 256>>>(nullptr, W2, b2);
    // agg3: Q3 = d*sum(P2)               hB -> hA    (F=64)
    k_agg<64, false, false, false, false><<<AGG64_BLK, 256>>>(nullptr);

    // pool at F=64 (+ node counts), then folded GEMM3 + MLP head
    k_pool64<<<(NNODES + 127) / 128, 64>>>(batch);
    k_mlp<<<NGRAPH, 128>>>(W3, b3, Wl1, bl1, Wl2, bl2, out);
}